// round 10
// baseline (speedup 1.0000x reference)
#include <cuda_runtime.h>
#include <cuda_fp16.h>
#include <cstdint>
#include <math.h>

#define EPSF 1e-5f

static const int N_TOK = 16384;   // B*T = 8*2048
static const int DIM   = 1024;
static const int FF    = 4096;

// ---------------- scratch (device globals; allocation-free) ----------------
__device__ __half   g_w1h[(size_t)FF * DIM];      // 8 MB  (quantized ints as half)
__device__ __half   g_w2h[(size_t)DIM * FF];      // 8 MB
__device__ __half   g_a1h[(size_t)N_TOK * DIM];   // 32 MB
__device__ __half   g_a2h[(size_t)N_TOK * FF];    // 128 MB
__device__ float    g_h  [(size_t)N_TOK * FF];    // 256 MB
__device__ float    g_dqa1[N_TOK];
__device__ unsigned g_hmax[N_TOK];                // float bits, idempotent max
__device__ unsigned g_wmax[2];                    // float bits

// ---------------- small PTX helpers ----------------
__device__ __forceinline__ void cp16(uint32_t dst, const void* src) {
    asm volatile("cp.async.cg.shared.global [%0], [%1], 16;\n" :: "r"(dst), "l"(src));
}
__device__ __forceinline__ void cp_arrive_noinc(uint32_t mbar) {
    asm volatile("cp.async.mbarrier.arrive.noinc.shared::cta.b64 [%0];\n" :: "r"(mbar) : "memory");
}
__device__ __forceinline__ void mbar_init(uint32_t mbar, uint32_t cnt) {
    asm volatile("mbarrier.init.shared.b64 [%0], %1;" :: "r"(mbar), "r"(cnt) : "memory");
}
__device__ __forceinline__ void mbar_arrive(uint32_t mbar) {
    asm volatile("mbarrier.arrive.shared.b64 _, [%0];" :: "r"(mbar) : "memory");
}
__device__ __forceinline__ void mbar_wait(uint32_t mbar, uint32_t parity) {
    uint32_t done;
    do {
        asm volatile("{\n\t.reg .pred p;\n\t"
            "mbarrier.try_wait.parity.acquire.cta.shared::cta.b64 p, [%1], %2, 0x989680;\n\t"
            "selp.b32 %0, 1, 0, p;\n\t}" : "=r"(done) : "r"(mbar), "r"(parity) : "memory");
    } while (!done);
}
__device__ __forceinline__ void ldsm4(uint32_t& r0, uint32_t& r1, uint32_t& r2, uint32_t& r3,
                                      uint32_t addr) {
    asm volatile("ldmatrix.sync.aligned.m8n8.x4.shared.b16 {%0,%1,%2,%3}, [%4];"
                 : "=r"(r0), "=r"(r1), "=r"(r2), "=r"(r3) : "r"(addr));
}
#define HMMA16816(acc, a0, a1, a2, a3, b0, b1) \
    asm volatile("mma.sync.aligned.m16n8k16.row.col.f32.f16.f16.f32 " \
                 "{%0,%1,%2,%3}, {%4,%5,%6,%7}, {%8,%9}, {%0,%1,%2,%3};\n" \
                 : "+f"((acc)[0]), "+f"((acc)[1]), "+f"((acc)[2]), "+f"((acc)[3]) \
                 : "r"(a0), "r"(a1), "r"(a2), "r"(a3), "r"(b0), "r"(b1))

// ======================= warp-specialized fp16 GEMM =======================
// BM=128, BN=128, BK=64. 384 threads: warps 0-7 consumers (2m x 4n, warp tile
// 64x32 — R8's proven mapping), warps 8-11 producers (one per SMSP).
// 5-stage smem ring (160KB), mbarrier full/empty per stage; NO __syncthreads
// in the mainloop. full[s]: init 128, producer cp.async completion-arrives.
// empty[s]: init 256, consumers arrive after the slab's ldsm reads.
//
// EPI==1: g_h = swish(dq(a1 @ w1^T) + b1), row absmax -> g_hmax
// EPI==2: out = x + 0.5*mask*(dq(a2 @ w2^T) + b2)
template<int EPI>
__launch_bounds__(384, 1)
__global__ void gemm_ws_k(const float* __restrict__ bias,
                          const float* __restrict__ xres,
                          const float* __restrict__ mask,
                          float* __restrict__ out) {
    constexpr int K   = (EPI == 1) ? DIM : FF;       // elements (halves)
    constexpr int KT  = K / 64;                      // BK=64 slabs
    constexpr int NST = 5;
    constexpr int STAGE = 128 * 128 * 2;             // A 16KB + B 16KB = 32KB

    const __half* __restrict__ A  = (EPI == 1) ? g_a1h : g_a2h;
    const __half* __restrict__ Bw = (EPI == 1) ? g_w1h : g_w2h;

    extern __shared__ int8_t sm[];                   // 5*32KB tiles + barriers
    const uint32_t smbase  = (uint32_t)__cvta_generic_to_shared(sm);
    const uint32_t barbase = smbase + NST * STAGE;   // full[s]=+16s, empty[s]=+16s+8

    const int tid  = threadIdx.x;
    const int lane = tid & 31;
    const int warp = tid >> 5;
    const int bm   = blockIdx.y * 128;
    const int bn   = blockIdx.x * 128;

    if (tid == 0) {
        #pragma unroll
        for (int s = 0; s < NST; s++) {
            mbar_init(barbase + s * 16, 128);        // full: 128 producer threads
            mbar_init(barbase + s * 16 + 8, 256);    // empty: 256 consumer threads
        }
    }
    __syncthreads();

    if (warp >= 8) {
        // ---------------- producer ----------------
        const int pt = tid - 256;                    // 0..127
        for (int kt = 0; kt < KT; ++kt) {
            const int s = kt % NST, r = kt / NST;
            if (r > 0) mbar_wait(barbase + s * 16 + 8, (r - 1) & 1);
            const uint32_t ab = smbase + s * STAGE;
            const uint32_t bb = ab + 128 * 128;
            #pragma unroll
            for (int i = 0; i < 8; i++) {            // A: 1024 chunks of 16B
                int c = pt + i * 128;
                int row = c >> 3, ch = c & 7;
                uint32_t dst = ab + row * 128 + ((ch ^ (row & 7)) << 4);
                cp16(dst, (const int8_t*)A + (size_t)(bm + row) * (K * 2) + kt * 128 + ch * 16);
            }
            #pragma unroll
            for (int i = 0; i < 8; i++) {            // B: 1024 chunks of 16B
                int c = pt + i * 128;
                int row = c >> 3, ch = c & 7;
                uint32_t dst = bb + row * 128 + ((ch ^ (row & 7)) << 4);
                cp16(dst, (const int8_t*)Bw + (size_t)(bn + row) * (K * 2) + kt * 128 + ch * 16);
            }
            cp_arrive_noinc(barbase + s * 16);
        }
        return;
    }

    // ---------------- consumer ----------------
    const int wm = warp >> 2;                        // 0..1
    const int wn = warp & 3;                         // 0..3

    float acc[4][4][4];
    #pragma unroll
    for (int mi = 0; mi < 4; mi++)
        #pragma unroll
        for (int ni = 0; ni < 4; ni++)
            #pragma unroll
            for (int j = 0; j < 4; j++) acc[mi][ni][j] = 0.f;

    for (int kt = 0; kt < KT; ++kt) {
        const int s = kt % NST, r = kt / NST;
        mbar_wait(barbase + s * 16, r & 1);

        const uint32_t abase = smbase + s * STAGE;
        const uint32_t bbase = abase + 128 * 128;

        #pragma unroll
        for (int ks = 0; ks < 4; ++ks) {             // four k16 steps per slab
            uint32_t af[4][4], bf[4][2];
            #pragma unroll
            for (int mi = 0; mi < 4; mi++) {
                int row = wm * 64 + mi * 16 + (lane & 15);
                int ch  = 2 * ks + (lane >> 4);
                uint32_t a = abase + row * 128 + ((ch ^ (row & 7)) << 4);
                ldsm4(af[mi][0], af[mi][1], af[mi][2], af[mi][3], a);
            }
            #pragma unroll
            for (int p = 0; p < 2; p++) {
                int row = wn * 32 + p * 16 + ((lane >> 4) << 3) + (lane & 7);
                int ch  = 2 * ks + ((lane >> 3) & 1);
                uint32_t a = bbase + row * 128 + ((ch ^ (row & 7)) << 4);
                ldsm4(bf[2 * p][0], bf[2 * p][1], bf[2 * p + 1][0], bf[2 * p + 1][1], a);
            }
            #pragma unroll
            for (int mi = 0; mi < 4; mi++)
                #pragma unroll
                for (int ni = 0; ni < 4; ni++)
                    HMMA16816(acc[mi][ni], af[mi][0], af[mi][1], af[mi][2], af[mi][3],
                              bf[ni][0], bf[ni][1]);
        }
        mbar_arrive(barbase + s * 16 + 8);           // stage consumed (ldsm done)
    }

    // ---------------- epilogue (R8's proven mapping) ----------------
    const float dqw = fmaxf(__uint_as_float(g_wmax[EPI - 1]), EPSF) * (1.f / 127.f);

    if (EPI == 1) {
        #pragma unroll
        for (int mi = 0; mi < 4; mi++) {
            #pragma unroll
            for (int half = 0; half < 2; ++half) {
                int row = bm + wm * 64 + mi * 16 + (lane >> 2) + half * 8;
                float f = g_dqa1[row] * dqw;
                float rmax = 0.f;
                #pragma unroll
                for (int ni = 0; ni < 4; ni++) {
                    #pragma unroll
                    for (int j = 0; j < 2; j++) {
                        int col = bn + wn * 32 + ni * 8 + (lane & 3) * 2 + j;
                        float v  = acc[mi][ni][half * 2 + j] * f + __ldg(&bias[col]);
                        float hv = v / (1.f + __expf(-v));     // v * sigmoid(v)
                        g_h[(size_t)row * FF + col] = hv;
                        rmax = fmaxf(rmax, fabsf(hv));
                    }
                }
                rmax = fmaxf(rmax, __shfl_xor_sync(0xffffffffu, rmax, 1));
                rmax = fmaxf(rmax, __shfl_xor_sync(0xffffffffu, rmax, 2));
                if ((lane & 3) == 0) atomicMax(&g_hmax[row], __float_as_uint(rmax));
            }
        }
    } else {
        #pragma unroll
        for (int mi = 0; mi < 4; mi++) {
            #pragma unroll
            for (int half = 0; half < 2; ++half) {
                int row = bm + wm * 64 + mi * 16 + (lane >> 2) + half * 8;
                float f  = fmaxf(__uint_as_float(g_hmax[row]), EPSF) * (1.f / 127.f) * dqw;
                float mk = mask[row];
                #pragma unroll
                for (int ni = 0; ni < 4; ni++) {
                    #pragma unroll
                    for (int j = 0; j < 2; j++) {
                        int col = bn + wn * 32 + ni * 8 + (lane & 3) * 2 + j;
                        float v = acc[mi][ni][half * 2 + j] * f + __ldg(&bias[col]);
                        out[(size_t)row * DIM + col] =
                            xres[(size_t)row * DIM + col] + 0.5f * v * mk;
                    }
                }
            }
        }
    }
}

// ======================= elementwise kernels =======================
__global__ void absmax_both_k(const float4* __restrict__ w1,
                              const float4* __restrict__ w2, int n4) {
    const int wi = blockIdx.y;
    const float4* __restrict__ x = wi ? w2 : w1;
    float m = 0.f;
    for (int i = blockIdx.x * blockDim.x + threadIdx.x; i < n4; i += gridDim.x * blockDim.x) {
        float4 v = x[i];
        m = fmaxf(m, fmaxf(fmaxf(fabsf(v.x), fabsf(v.y)), fmaxf(fabsf(v.z), fabsf(v.w))));
    }
    #pragma unroll
    for (int o = 16; o; o >>= 1) m = fmaxf(m, __shfl_xor_sync(0xffffffffu, m, o));
    __shared__ float sh[32];
    if ((threadIdx.x & 31) == 0) sh[threadIdx.x >> 5] = m;
    __syncthreads();
    if (threadIdx.x < 32) {
        m = (threadIdx.x < (blockDim.x >> 5)) ? sh[threadIdx.x] : 0.f;
        #pragma unroll
        for (int o = 16; o; o >>= 1) m = fmaxf(m, __shfl_xor_sync(0xffffffffu, m, o));
        if (threadIdx.x == 0) atomicMax(&g_wmax[wi], __float_as_uint(m));
    }
}

__global__ void quantw_both_k(const float4* __restrict__ w1,
                              const float4* __restrict__ w2, int n4) {
    const int wi = blockIdx.y;
    const float4* __restrict__ w = wi ? w2 : w1;
    int i = blockIdx.x * blockDim.x + threadIdx.x;
    if (i >= n4) return;
    float s = 127.f / fmaxf(__uint_as_float(g_wmax[wi]), EPSF);
    float4 v = w[i];
    __half2 h0 = __floats2half2_rn(rintf(fminf(fmaxf(v.x * s, -127.f), 127.f)),
                                   rintf(fminf(fmaxf(v.y * s, -127.f), 127.f)));
    __half2 h1 = __floats2half2_rn(rintf(fminf(fmaxf(v.z * s, -127.f), 127.f)),
                                   rintf(fminf(fmaxf(v.w * s, -127.f), 127.f)));
    __half2* dst = (__half2*)(wi ? g_w2h : g_w1h);
    dst[2 * i]     = h0;
    dst[2 * i + 1] = h1;
}

__global__ void ln_quant_k(const float4* __restrict__ x,
                           const float4* __restrict__ gamma,
                           const float4* __restrict__ beta) {
    const int row = blockIdx.x;
    const int t   = threadIdx.x;
    __shared__ float sh[8];

    float4 v = x[(size_t)row * 256 + t];
    float s = v.x + v.y + v.z + v.w;
    #pragma unroll
    for (int o = 16; o; o >>= 1) s += __shfl_xor_sync(0xffffffffu, s, o);
    if ((t & 31) == 0) sh[t >> 5] = s;
    __syncthreads();
    float mu = sh[0];
    #pragma unroll
    for (int i = 1; i < 8; i++) mu += sh[i];
    mu *= (1.f / 1024.f);
    __syncthreads();

    float d0 = v.x - mu, d1 = v.y - mu, d2 = v.z - mu, d3 = v.w - mu;
    float ss = d0*d0 + d1*d1 + d2*d2 + d3*d3;
    #pragma unroll
    for (int o = 16; o; o >>= 1) ss += __shfl_xor_sync(0xffffffffu, ss, o);
    if ((t & 31) == 0) sh[t >> 5] = ss;
    __syncthreads();
    float var = sh[0];
    #pragma unroll
    for (int i = 1; i < 8; i++) var += sh[i];
    var *= (1.f / 1024.f);
    __syncthreads();

    float rstd = rsqrtf(var + EPSF);
    float4 g = gamma[t], b = beta[t];
    float y0 = d0 * rstd * g.x + b.x;
    float y1 = d1 * rstd * g.y + b.y;
    float y2 = d2 * rstd * g.z + b.z;
    float y3 = d3 * rstd * g.w + b.w;

    float am = fmaxf(fmaxf(fabsf(y0), fabsf(y1)), fmaxf(fabsf(y2), fabsf(y3)));
    #pragma unroll
    for (int o = 16; o; o >>= 1) am = fmaxf(am, __shfl_xor_sync(0xffffffffu, am, o));
    if ((t & 31) == 0) sh[t >> 5] = am;
    __syncthreads();
    float amax = sh[0];
    #pragma unroll
    for (int i = 1; i < 8; i++) amax = fmaxf(amax, sh[i]);

    amax = fmaxf(amax, EPSF);
    float sc = 127.f / amax;
    __half2 h0 = __floats2half2_rn(rintf(fminf(fmaxf(y0 * sc, -127.f), 127.f)),
                                   rintf(fminf(fmaxf(y1 * sc, -127.f), 127.f)));
    __half2 h1 = __floats2half2_rn(rintf(fminf(fmaxf(y2 * sc, -127.f), 127.f)),
                                   rintf(fminf(fmaxf(y3 * sc, -127.f), 127.f)));
    __half2* dst = (__half2*)g_a1h;
    dst[(size_t)row * 512 + 2 * t]     = h0;
    dst[(size_t)row * 512 + 2 * t + 1] = h1;
    if (t == 0) g_dqa1[row] = amax * (1.f / 127.f);
}

__global__ void quant_h_k() {
    size_t gid = (size_t)blockIdx.x * blockDim.x + threadIdx.x;
    size_t i = gid * 2;
    const float4* __restrict__ src = (const float4*)g_h;
    __half2* __restrict__ dst = (__half2*)g_a2h;
    #pragma unroll
    for (int u = 0; u < 2; u++) {
        size_t idx = i + u;
        int row = (int)(idx >> 10);
        float s = 127.f / fmaxf(__uint_as_float(g_hmax[row]), EPSF);
        float4 v = src[idx];
        __half2 h0 = __floats2half2_rn(rintf(fminf(fmaxf(v.x * s, -127.f), 127.f)),
                                       rintf(fminf(fmaxf(v.y * s, -127.f), 127.f)));
        __half2 h1 = __floats2half2_rn(rintf(fminf(fmaxf(v.z * s, -127.f), 127.f)),
                                       rintf(fminf(fmaxf(v.w * s, -127.f), 127.f)));
        dst[2 * idx]     = h0;
        dst[2 * idx + 1] = h1;
    }
}

// ======================= launcher =======================
extern "C" void kernel_launch(void* const* d_in, const int* in_sizes, int n_in,
                              void* d_out, int out_size) {
    const float* x     = (const float*)d_in[0];
    const float* mask  = (const float*)d_in[1];
    const float* gamma = (const float*)d_in[2];
    const float* beta  = (const float*)d_in[3];
    const float* w1    = (const float*)d_in[4];
    const float* b1    = (const float*)d_in[5];
    const float* w2    = (const float*)d_in[6];
    const float* b2    = (const float*)d_in[7];
    float* out = (float*)d_out;

    const int wn4 = (FF * DIM) / 4;
    const int WS_SMEM = 5 * 128 * 128 * 2 + 256;     // 160KB tiles + barriers
    cudaFuncSetAttribute(gemm_ws_k<1>, cudaFuncAttributeMaxDynamicSharedMemorySize, WS_SMEM);
    cudaFuncSetAttribute(gemm_ws_k<2>, cudaFuncAttributeMaxDynamicSharedMemorySize, WS_SMEM);

    // weights: absmax -> quantize to fp16 ints (idempotent across graph replays)
    absmax_both_k<<<dim3(1024, 2), 256>>>((const float4*)w1, (const float4*)w2, wn4);
    quantw_both_k<<<dim3(wn4 / 256, 2), 256>>>((const float4*)w1, (const float4*)w2, wn4);

    // LN + per-token act quant -> fp16 ints
    ln_quant_k<<<N_TOK, 256>>>((const float4*)x, (const float4*)gamma, (const float4*)beta);

    // GEMM1 + swish + row absmax (warp-specialized)
    gemm_ws_k<1><<<dim3(FF / 128, N_TOK / 128), 384, WS_SMEM>>>(b1, nullptr, nullptr, nullptr);

    // quantize h -> fp16 ints
    quant_h_k<<<(N_TOK * (FF / 4)) / 512, 256>>>();

    // GEMM2 + residual (warp-specialized)
    gemm_ws_k<2><<<dim3(DIM / 128, N_TOK / 128), 384, WS_SMEM>>>(b2, x, mask, out);
}

// round 11
// speedup vs baseline: 1.0013x; 1.0013x over previous
#include <cuda_runtime.h>
#include <cuda_fp16.h>
#include <cstdint>
#include <math.h>

#define EPSF 1e-5f

static const int N_TOK = 16384;   // B*T = 8*2048
static const int DIM   = 1024;
static const int FF    = 4096;

// ---------------- scratch (device globals; allocation-free) ----------------
__device__ __half   g_w1h[(size_t)FF * DIM];      // 8 MB  (quantized ints as half)
__device__ __half   g_w2h[(size_t)DIM * FF];      // 8 MB
__device__ __half   g_a1h[(size_t)N_TOK * DIM];   // 32 MB
__device__ __half   g_a2h[(size_t)N_TOK * FF];    // 128 MB
__device__ float    g_h  [(size_t)N_TOK * FF];    // 256 MB
__device__ float    g_dqa1[N_TOK];
__device__ unsigned g_hmax[N_TOK];                // float bits, idempotent max
__device__ unsigned g_wmax[2];                    // float bits

// ---------------- small PTX helpers ----------------
__device__ __forceinline__ void cp16(uint32_t dst, const void* src) {
    asm volatile("cp.async.cg.shared.global [%0], [%1], 16;\n" :: "r"(dst), "l"(src));
}
__device__ __forceinline__ void cp_commit() { asm volatile("cp.async.commit_group;\n"); }
template<int N> __device__ __forceinline__ void cp_wait() {
    asm volatile("cp.async.wait_group %0;\n" :: "n"(N));
}
__device__ __forceinline__ void ldsm4(uint32_t& r0, uint32_t& r1, uint32_t& r2, uint32_t& r3,
                                      uint32_t addr) {
    asm volatile("ldmatrix.sync.aligned.m8n8.x4.shared.b16 {%0,%1,%2,%3}, [%4];"
                 : "=r"(r0), "=r"(r1), "=r"(r2), "=r"(r3) : "r"(addr));
}
#define HMMA16816(acc, a0, a1, a2, a3, b0, b1) \
    asm volatile("mma.sync.aligned.m16n8k16.row.col.f32.f16.f16.f32 " \
                 "{%0,%1,%2,%3}, {%4,%5,%6,%7}, {%8,%9}, {%0,%1,%2,%3};\n" \
                 : "+f"((acc)[0]), "+f"((acc)[1]), "+f"((acc)[2]), "+f"((acc)[3]) \
                 : "r"(a0), "r"(a1), "r"(a2), "r"(a3), "r"(b0), "r"(b1))

// ======================= fp16 GEMM via mma.sync m16n8k16 =======================
// Operands are quantized integers stored as fp16 (exact); accumulate fp32.
// BM=128, BN=128, BK=64 (128B rows). 512 threads = 16 warps as 4(m) x 4(n),
// warp tile 32x32 (acc = 32 regs). 3-stage cp.async pipeline, 96KB smem/CTA,
// 2 CTAs/SM -> 32 warps/SM = 8 per SMSP for deep latency hiding.
// Smem swizzle: 16B chunk' = chunk ^ (row & 7)  (8 chunks per 128B row).
//
// EPI==1: g_h = swish(dq(a1 @ w1^T) + b1), row absmax -> g_hmax
// EPI==2: out = x + 0.5*mask*(dq(a2 @ w2^T) + b2)
template<int EPI>
__launch_bounds__(512, 2)
__global__ void gemm_f16_k(const float* __restrict__ bias,
                           const float* __restrict__ xres,
                           const float* __restrict__ mask,
                           float* __restrict__ out) {
    constexpr int K  = (EPI == 1) ? DIM : FF;        // elements (halves)
    constexpr int KT = K / 64;                       // BK=64 slabs
    constexpr int STAGE = 128 * 128 * 2;             // A 16KB + B 16KB = 32KB

    const __half* __restrict__ A  = (EPI == 1) ? g_a1h : g_a2h;
    const __half* __restrict__ Bw = (EPI == 1) ? g_w1h : g_w2h;

    extern __shared__ int8_t sm[];                   // 3 * 32KB

    const int tid  = threadIdx.x;
    const int lane = tid & 31;
    const int warp = tid >> 5;                       // 0..15
    const int wm   = warp >> 2;                      // 0..3
    const int wn   = warp & 3;                       // 0..3
    const int bm   = blockIdx.y * 128;
    const int bn   = blockIdx.x * 128;

    float acc[2][4][4];
    #pragma unroll
    for (int mi = 0; mi < 2; mi++)
        #pragma unroll
        for (int ni = 0; ni < 4; ni++)
            #pragma unroll
            for (int j = 0; j < 4; j++) acc[mi][ni][j] = 0.f;

    auto ld_stage = [&](int stg, int kt) {
        uint32_t ab = (uint32_t)__cvta_generic_to_shared(sm + stg * STAGE);
        uint32_t bb = ab + 128 * 128;
        #pragma unroll
        for (int i = 0; i < 2; i++) {                // A: 1024 chunks of 16B
            int c = tid + i * 512;
            int row = c >> 3, ch = c & 7;
            uint32_t dst = ab + row * 128 + ((ch ^ (row & 7)) << 4);
            cp16(dst, (const int8_t*)A + (size_t)(bm + row) * (K * 2) + kt * 128 + ch * 16);
        }
        #pragma unroll
        for (int i = 0; i < 2; i++) {                // B: 1024 chunks of 16B
            int c = tid + i * 512;
            int row = c >> 3, ch = c & 7;
            uint32_t dst = bb + row * 128 + ((ch ^ (row & 7)) << 4);
            cp16(dst, (const int8_t*)Bw + (size_t)(bn + row) * (K * 2) + kt * 128 + ch * 16);
        }
        cp_commit();
    };

    ld_stage(0, 0);
    ld_stage(1, 1);

    for (int kt = 0; kt < KT; ++kt) {
        if (kt + 2 < KT) { cp_wait<1>(); } else { cp_wait<0>(); }
        __syncthreads();
        if (kt + 2 < KT) ld_stage((kt + 2) % 3, kt + 2);

        uint32_t abase = (uint32_t)__cvta_generic_to_shared(sm + (kt % 3) * STAGE);
        uint32_t bbase = abase + 128 * 128;

        #pragma unroll
        for (int ks = 0; ks < 4; ++ks) {             // four k16 steps per slab
            uint32_t af[2][4], bf[4][2];
            #pragma unroll
            for (int mi = 0; mi < 2; mi++) {         // A: 32 rows x k16
                int row = wm * 32 + mi * 16 + (lane & 15);
                int ch  = 2 * ks + (lane >> 4);
                uint32_t a = abase + row * 128 + ((ch ^ (row & 7)) << 4);
                ldsm4(af[mi][0], af[mi][1], af[mi][2], af[mi][3], a);
            }
            #pragma unroll
            for (int p = 0; p < 2; p++) {            // B: 32 rows x k16
                int row = wn * 32 + p * 16 + ((lane >> 4) << 3) + (lane & 7);
                int ch  = 2 * ks + ((lane >> 3) & 1);
                uint32_t a = bbase + row * 128 + ((ch ^ (row & 7)) << 4);
                ldsm4(bf[2 * p][0], bf[2 * p][1], bf[2 * p + 1][0], bf[2 * p + 1][1], a);
            }
            #pragma unroll
            for (int mi = 0; mi < 2; mi++)
                #pragma unroll
                for (int ni = 0; ni < 4; ni++)
                    HMMA16816(acc[mi][ni], af[mi][0], af[mi][1], af[mi][2], af[mi][3],
                              bf[ni][0], bf[ni][1]);
        }
    }

    // ---------------- epilogue (16-warp 4x4, warp tile 32x32) ----------------
    const float dqw = fmaxf(__uint_as_float(g_wmax[EPI - 1]), EPSF) * (1.f / 127.f);

    if (EPI == 1) {
        #pragma unroll
        for (int mi = 0; mi < 2; mi++) {
            #pragma unroll
            for (int half = 0; half < 2; ++half) {
                int row = bm + wm * 32 + mi * 16 + (lane >> 2) + half * 8;
                float f = g_dqa1[row] * dqw;
                float rmax = 0.f;
                #pragma unroll
                for (int ni = 0; ni < 4; ni++) {
                    #pragma unroll
                    for (int j = 0; j < 2; j++) {
                        int col = bn + wn * 32 + ni * 8 + (lane & 3) * 2 + j;
                        float v  = acc[mi][ni][half * 2 + j] * f + __ldg(&bias[col]);
                        float hv = v / (1.f + __expf(-v));     // v * sigmoid(v)
                        g_h[(size_t)row * FF + col] = hv;
                        rmax = fmaxf(rmax, fabsf(hv));
                    }
                }
                rmax = fmaxf(rmax, __shfl_xor_sync(0xffffffffu, rmax, 1));
                rmax = fmaxf(rmax, __shfl_xor_sync(0xffffffffu, rmax, 2));
                if ((lane & 3) == 0) atomicMax(&g_hmax[row], __float_as_uint(rmax));
            }
        }
    } else {
        #pragma unroll
        for (int mi = 0; mi < 2; mi++) {
            #pragma unroll
            for (int half = 0; half < 2; ++half) {
                int row = bm + wm * 32 + mi * 16 + (lane >> 2) + half * 8;
                float f  = fmaxf(__uint_as_float(g_hmax[row]), EPSF) * (1.f / 127.f) * dqw;
                float mk = mask[row];
                #pragma unroll
                for (int ni = 0; ni < 4; ni++) {
                    #pragma unroll
                    for (int j = 0; j < 2; j++) {
                        int col = bn + wn * 32 + ni * 8 + (lane & 3) * 2 + j;
                        float v = acc[mi][ni][half * 2 + j] * f + __ldg(&bias[col]);
                        out[(size_t)row * DIM + col] =
                            xres[(size_t)row * DIM + col] + 0.5f * v * mk;
                    }
                }
            }
        }
    }
}

// ======================= elementwise kernels =======================
__global__ void absmax_both_k(const float4* __restrict__ w1,
                              const float4* __restrict__ w2, int n4) {
    const int wi = blockIdx.y;
    const float4* __restrict__ x = wi ? w2 : w1;
    float m = 0.f;
    for (int i = blockIdx.x * blockDim.x + threadIdx.x; i < n4; i += gridDim.x * blockDim.x) {
        float4 v = x[i];
        m = fmaxf(m, fmaxf(fmaxf(fabsf(v.x), fabsf(v.y)), fmaxf(fabsf(v.z), fabsf(v.w))));
    }
    #pragma unroll
    for (int o = 16; o; o >>= 1) m = fmaxf(m, __shfl_xor_sync(0xffffffffu, m, o));
    __shared__ float sh[32];
    if ((threadIdx.x & 31) == 0) sh[threadIdx.x >> 5] = m;
    __syncthreads();
    if (threadIdx.x < 32) {
        m = (threadIdx.x < (blockDim.x >> 5)) ? sh[threadIdx.x] : 0.f;
        #pragma unroll
        for (int o = 16; o; o >>= 1) m = fmaxf(m, __shfl_xor_sync(0xffffffffu, m, o));
        if (threadIdx.x == 0) atomicMax(&g_wmax[wi], __float_as_uint(m));
    }
}

__global__ void quantw_both_k(const float4* __restrict__ w1,
                              const float4* __restrict__ w2, int n4) {
    const int wi = blockIdx.y;
    const float4* __restrict__ w = wi ? w2 : w1;
    int i = blockIdx.x * blockDim.x + threadIdx.x;
    if (i >= n4) return;
    float s = 127.f / fmaxf(__uint_as_float(g_wmax[wi]), EPSF);
    float4 v = w[i];
    __half2 h0 = __floats2half2_rn(rintf(fminf(fmaxf(v.x * s, -127.f), 127.f)),
                                   rintf(fminf(fmaxf(v.y * s, -127.f), 127.f)));
    __half2 h1 = __floats2half2_rn(rintf(fminf(fmaxf(v.z * s, -127.f), 127.f)),
                                   rintf(fminf(fmaxf(v.w * s, -127.f), 127.f)));
    __half2* dst = (__half2*)(wi ? g_w2h : g_w1h);
    dst[2 * i]     = h0;
    dst[2 * i + 1] = h1;
}

__global__ void ln_quant_k(const float4* __restrict__ x,
                           const float4* __restrict__ gamma,
                           const float4* __restrict__ beta) {
    const int row = blockIdx.x;
    const int t   = threadIdx.x;
    __shared__ float sh[8];

    float4 v = x[(size_t)row * 256 + t];
    float s = v.x + v.y + v.z + v.w;
    #pragma unroll
    for (int o = 16; o; o >>= 1) s += __shfl_xor_sync(0xffffffffu, s, o);
    if ((t & 31) == 0) sh[t >> 5] = s;
    __syncthreads();
    float mu = sh[0];
    #pragma unroll
    for (int i = 1; i < 8; i++) mu += sh[i];
    mu *= (1.f / 1024.f);
    __syncthreads();

    float d0 = v.x - mu, d1 = v.y - mu, d2 = v.z - mu, d3 = v.w - mu;
    float ss = d0*d0 + d1*d1 + d2*d2 + d3*d3;
    #pragma unroll
    for (int o = 16; o; o >>= 1) ss += __shfl_xor_sync(0xffffffffu, ss, o);
    if ((t & 31) == 0) sh[t >> 5] = ss;
    __syncthreads();
    float var = sh[0];
    #pragma unroll
    for (int i = 1; i < 8; i++) var += sh[i];
    var *= (1.f / 1024.f);
    __syncthreads();

    float rstd = rsqrtf(var + EPSF);
    float4 g = gamma[t], b = beta[t];
    float y0 = d0 * rstd * g.x + b.x;
    float y1 = d1 * rstd * g.y + b.y;
    float y2 = d2 * rstd * g.z + b.z;
    float y3 = d3 * rstd * g.w + b.w;

    float am = fmaxf(fmaxf(fabsf(y0), fabsf(y1)), fmaxf(fabsf(y2), fabsf(y3)));
    #pragma unroll
    for (int o = 16; o; o >>= 1) am = fmaxf(am, __shfl_xor_sync(0xffffffffu, am, o));
    if ((t & 31) == 0) sh[t >> 5] = am;
    __syncthreads();
    float amax = sh[0];
    #pragma unroll
    for (int i = 1; i < 8; i++) amax = fmaxf(amax, sh[i]);

    amax = fmaxf(amax, EPSF);
    float sc = 127.f / amax;
    __half2 h0 = __floats2half2_rn(rintf(fminf(fmaxf(y0 * sc, -127.f), 127.f)),
                                   rintf(fminf(fmaxf(y1 * sc, -127.f), 127.f)));
    __half2 h1 = __floats2half2_rn(rintf(fminf(fmaxf(y2 * sc, -127.f), 127.f)),
                                   rintf(fminf(fmaxf(y3 * sc, -127.f), 127.f)));
    __half2* dst = (__half2*)g_a1h;
    dst[(size_t)row * 512 + 2 * t]     = h0;
    dst[(size_t)row * 512 + 2 * t + 1] = h1;
    if (t == 0) g_dqa1[row] = amax * (1.f / 127.f);
}

__global__ void quant_h_k() {
    size_t gid = (size_t)blockIdx.x * blockDim.x + threadIdx.x;
    size_t i = gid * 2;
    const float4* __restrict__ src = (const float4*)g_h;
    __half2* __restrict__ dst = (__half2*)g_a2h;
    #pragma unroll
    for (int u = 0; u < 2; u++) {
        size_t idx = i + u;
        int row = (int)(idx >> 10);
        float s = 127.f / fmaxf(__uint_as_float(g_hmax[row]), EPSF);
        float4 v = src[idx];
        __half2 h0 = __floats2half2_rn(rintf(fminf(fmaxf(v.x * s, -127.f), 127.f)),
                                       rintf(fminf(fmaxf(v.y * s, -127.f), 127.f)));
        __half2 h1 = __floats2half2_rn(rintf(fminf(fmaxf(v.z * s, -127.f), 127.f)),
                                       rintf(fminf(fmaxf(v.w * s, -127.f), 127.f)));
        dst[2 * idx]     = h0;
        dst[2 * idx + 1] = h1;
    }
}

// ======================= launcher =======================
extern "C" void kernel_launch(void* const* d_in, const int* in_sizes, int n_in,
                              void* d_out, int out_size) {
    const float* x     = (const float*)d_in[0];
    const float* mask  = (const float*)d_in[1];
    const float* gamma = (const float*)d_in[2];
    const float* beta  = (const float*)d_in[3];
    const float* w1    = (const float*)d_in[4];
    const float* b1    = (const float*)d_in[5];
    const float* w2    = (const float*)d_in[6];
    const float* b2    = (const float*)d_in[7];
    float* out = (float*)d_out;

    const int wn4 = (FF * DIM) / 4;
    const int GEMM_SMEM = 3 * 128 * 128 * 2;       // 96KB
    cudaFuncSetAttribute(gemm_f16_k<1>, cudaFuncAttributeMaxDynamicSharedMemorySize, GEMM_SMEM);
    cudaFuncSetAttribute(gemm_f16_k<2>, cudaFuncAttributeMaxDynamicSharedMemorySize, GEMM_SMEM);

    // weights: absmax -> quantize to fp16 ints (idempotent across graph replays)
    absmax_both_k<<<dim3(1024, 2), 256>>>((const float4*)w1, (const float4*)w2, wn4);
    quantw_both_k<<<dim3(wn4 / 256, 2), 256>>>((const float4*)w1, (const float4*)w2, wn4);

    // LN + per-token act quant -> fp16 ints
    ln_quant_k<<<N_TOK, 256>>>((const float4*)x, (const float4*)gamma, (const float4*)beta);

    // GEMM1 + swish + row absmax
    gemm_f16_k<1><<<dim3(FF / 128, N_TOK / 128), 512, GEMM_SMEM>>>(b1, nullptr, nullptr, nullptr);

    // quantize h -> fp16 ints
    quant_h_k<<<(N_TOK * (FF / 4)) / 512, 256>>>();

    // GEMM2 + residual
    gemm_f16_k<2><<<dim3(DIM / 128, N_TOK / 128), 512, GEMM_SMEM>>>(b2, x, mask, out);
}

// round 12
// speedup vs baseline: 1.1344x; 1.1329x over previous
#include <cuda_runtime.h>
#include <cuda_fp16.h>
#include <cstdint>
#include <math.h>

#define EPSF 1e-5f

static const int N_TOK = 16384;   // B*T = 8*2048
static const int DIM   = 1024;
static const int FF    = 4096;

// ---------------- scratch (device globals; allocation-free) ----------------
__device__ __half   g_w1h[(size_t)FF * DIM];      // 8 MB  (quantized ints as half)
__device__ __half   g_w2h[(size_t)DIM * FF];      // 8 MB
__device__ __half   g_a1h[(size_t)N_TOK * DIM];   // 32 MB
__device__ __half   g_a2h[(size_t)N_TOK * FF];    // 128 MB
__device__ float    g_h  [(size_t)N_TOK * FF];    // 256 MB
__device__ float    g_dqa1[N_TOK];
__device__ unsigned g_hmax[N_TOK];                // float bits, idempotent max
__device__ unsigned g_wmax[2];                    // float bits

// ---------------- small PTX helpers ----------------
__device__ __forceinline__ void cp16(uint32_t dst, const void* src) {
    asm volatile("cp.async.cg.shared.global [%0], [%1], 16;\n" :: "r"(dst), "l"(src));
}
__device__ __forceinline__ void cp_commit() { asm volatile("cp.async.commit_group;\n"); }
template<int N> __device__ __forceinline__ void cp_wait() {
    asm volatile("cp.async.wait_group %0;\n" :: "n"(N));
}
__device__ __forceinline__ void ldsm4(uint32_t& r0, uint32_t& r1, uint32_t& r2, uint32_t& r3,
                                      uint32_t addr) {
    asm volatile("ldmatrix.sync.aligned.m8n8.x4.shared.b16 {%0,%1,%2,%3}, [%4];"
                 : "=r"(r0), "=r"(r1), "=r"(r2), "=r"(r3) : "r"(addr));
}
#define HMMA16816(acc, a0, a1, a2, a3, b0, b1) \
    asm volatile("mma.sync.aligned.m16n8k16.row.col.f32.f16.f16.f32 " \
                 "{%0,%1,%2,%3}, {%4,%5,%6,%7}, {%8,%9}, {%0,%1,%2,%3};\n" \
                 : "+f"((acc)[0]), "+f"((acc)[1]), "+f"((acc)[2]), "+f"((acc)[3]) \
                 : "r"(a0), "r"(a1), "r"(a2), "r"(a3), "r"(b0), "r"(b1))

// ======================= GEMM1 (R8 config, proven: 378us, tensor 60%) ==========
// BM=128, BN=128, BK=64. 256 threads = 8 warps 2(m) x 4(n), warp tile 64x32.
// 3-stage cp.async, 96KB, 2 CTAs/SM.
__launch_bounds__(256, 2)
__global__ void gemm1_f16_k(const float* __restrict__ bias) {
    constexpr int K  = DIM;
    constexpr int KT = K / 64;
    constexpr int STAGE = 128 * 128 * 2;             // 32KB

    const __half* __restrict__ A  = g_a1h;
    const __half* __restrict__ Bw = g_w1h;

    extern __shared__ int8_t sm[];

    const int tid  = threadIdx.x;
    const int lane = tid & 31;
    const int warp = tid >> 5;
    const int wm   = warp >> 2;
    const int wn   = warp & 3;
    const int bm   = blockIdx.y * 128;
    const int bn   = blockIdx.x * 128;

    float acc[4][4][4];
    #pragma unroll
    for (int mi = 0; mi < 4; mi++)
        #pragma unroll
        for (int ni = 0; ni < 4; ni++)
            #pragma unroll
            for (int j = 0; j < 4; j++) acc[mi][ni][j] = 0.f;

    auto ld_stage = [&](int stg, int kt) {
        uint32_t ab = (uint32_t)__cvta_generic_to_shared(sm + stg * STAGE);
        uint32_t bb = ab + 128 * 128;
        #pragma unroll
        for (int i = 0; i < 4; i++) {
            int c = tid + i * 256;
            int row = c >> 3, ch = c & 7;
            uint32_t dst = ab + row * 128 + ((ch ^ (row & 7)) << 4);
            cp16(dst, (const int8_t*)A + (size_t)(bm + row) * (K * 2) + kt * 128 + ch * 16);
        }
        #pragma unroll
        for (int i = 0; i < 4; i++) {
            int c = tid + i * 256;
            int row = c >> 3, ch = c & 7;
            uint32_t dst = bb + row * 128 + ((ch ^ (row & 7)) << 4);
            cp16(dst, (const int8_t*)Bw + (size_t)(bn + row) * (K * 2) + kt * 128 + ch * 16);
        }
        cp_commit();
    };

    ld_stage(0, 0);
    ld_stage(1, 1);

    for (int kt = 0; kt < KT; ++kt) {
        if (kt + 2 < KT) { cp_wait<1>(); } else { cp_wait<0>(); }
        __syncthreads();
        if (kt + 2 < KT) ld_stage((kt + 2) % 3, kt + 2);

        uint32_t abase = (uint32_t)__cvta_generic_to_shared(sm + (kt % 3) * STAGE);
        uint32_t bbase = abase + 128 * 128;

        #pragma unroll
        for (int ks = 0; ks < 4; ++ks) {
            uint32_t af[4][4], bf[4][2];
            #pragma unroll
            for (int mi = 0; mi < 4; mi++) {
                int row = wm * 64 + mi * 16 + (lane & 15);
                int ch  = 2 * ks + (lane >> 4);
                uint32_t a = abase + row * 128 + ((ch ^ (row & 7)) << 4);
                ldsm4(af[mi][0], af[mi][1], af[mi][2], af[mi][3], a);
            }
            #pragma unroll
            for (int p = 0; p < 2; p++) {
                int row = wn * 32 + p * 16 + ((lane >> 4) << 3) + (lane & 7);
                int ch  = 2 * ks + ((lane >> 3) & 1);
                uint32_t a = bbase + row * 128 + ((ch ^ (row & 7)) << 4);
                ldsm4(bf[2 * p][0], bf[2 * p][1], bf[2 * p + 1][0], bf[2 * p + 1][1], a);
            }
            #pragma unroll
            for (int mi = 0; mi < 4; mi++)
                #pragma unroll
                for (int ni = 0; ni < 4; ni++)
                    HMMA16816(acc[mi][ni], af[mi][0], af[mi][1], af[mi][2], af[mi][3],
                              bf[ni][0], bf[ni][1]);
        }
    }

    // epilogue: swish + store h + row absmax
    const float dqw = fmaxf(__uint_as_float(g_wmax[0]), EPSF) * (1.f / 127.f);
    #pragma unroll
    for (int mi = 0; mi < 4; mi++) {
        #pragma unroll
        for (int half = 0; half < 2; ++half) {
            int row = bm + wm * 64 + mi * 16 + (lane >> 2) + half * 8;
            float f = g_dqa1[row] * dqw;
            float rmax = 0.f;
            #pragma unroll
            for (int ni = 0; ni < 4; ni++) {
                #pragma unroll
                for (int j = 0; j < 2; j++) {
                    int col = bn + wn * 32 + ni * 8 + (lane & 3) * 2 + j;
                    float v  = acc[mi][ni][half * 2 + j] * f + __ldg(&bias[col]);
                    float hv = v / (1.f + __expf(-v));
                    g_h[(size_t)row * FF + col] = hv;
                    rmax = fmaxf(rmax, fabsf(hv));
                }
            }
            rmax = fmaxf(rmax, __shfl_xor_sync(0xffffffffu, rmax, 1));
            rmax = fmaxf(rmax, __shfl_xor_sync(0xffffffffu, rmax, 2));
            if ((lane & 3) == 0) atomicMax(&g_hmax[row], __float_as_uint(rmax));
        }
    }
}

// ======================= GEMM2: R8 tile + split-K=2 ===========================
// Same BM=128, BN=128, BK=64, 8 warps 2x4 (64x32), 3 stages, 2 CTAs/SM.
// gridDim.z = 2 splits of K=2048 each -> 2048 CTAs = 6.92 waves (99% util).
// out pre-initialized by ln_quant to x + 0.5*mask*b2; epilogue atomicAdds
// 0.5*mask*f*acc (fp32; order-independent up to ULP, tolerance 1e-3).
__launch_bounds__(256, 2)
__global__ void gemm2_f16_k(const float* __restrict__ mask,
                            float* __restrict__ out) {
    constexpr int K   = FF;
    constexpr int KSP = K / 2;                       // 2048 per split
    constexpr int KT  = KSP / 64;                    // 32 slabs
    constexpr int STAGE = 128 * 128 * 2;             // 32KB

    const __half* __restrict__ A  = g_a2h;
    const __half* __restrict__ Bw = g_w2h;

    extern __shared__ int8_t sm[];

    const int tid  = threadIdx.x;
    const int lane = tid & 31;
    const int warp = tid >> 5;
    const int wm   = warp >> 2;
    const int wn   = warp & 3;
    const int bm   = blockIdx.y * 128;
    const int bn   = blockIdx.x * 128;
    const int koff = blockIdx.z * (KSP * 2);         // byte offset into K dim

    float acc[4][4][4];
    #pragma unroll
    for (int mi = 0; mi < 4; mi++)
        #pragma unroll
        for (int ni = 0; ni < 4; ni++)
            #pragma unroll
            for (int j = 0; j < 4; j++) acc[mi][ni][j] = 0.f;

    auto ld_stage = [&](int stg, int kt) {
        uint32_t ab = (uint32_t)__cvta_generic_to_shared(sm + stg * STAGE);
        uint32_t bb = ab + 128 * 128;
        #pragma unroll
        for (int i = 0; i < 4; i++) {
            int c = tid + i * 256;
            int row = c >> 3, ch = c & 7;
            uint32_t dst = ab + row * 128 + ((ch ^ (row & 7)) << 4);
            cp16(dst, (const int8_t*)A + (size_t)(bm + row) * (K * 2) + koff + kt * 128 + ch * 16);
        }
        #pragma unroll
        for (int i = 0; i < 4; i++) {
            int c = tid + i * 256;
            int row = c >> 3, ch = c & 7;
            uint32_t dst = bb + row * 128 + ((ch ^ (row & 7)) << 4);
            cp16(dst, (const int8_t*)Bw + (size_t)(bn + row) * (K * 2) + koff + kt * 128 + ch * 16);
        }
        cp_commit();
    };

    ld_stage(0, 0);
    ld_stage(1, 1);

    for (int kt = 0; kt < KT; ++kt) {
        if (kt + 2 < KT) { cp_wait<1>(); } else { cp_wait<0>(); }
        __syncthreads();
        if (kt + 2 < KT) ld_stage((kt + 2) % 3, kt + 2);

        uint32_t abase = (uint32_t)__cvta_generic_to_shared(sm + (kt % 3) * STAGE);
        uint32_t bbase = abase + 128 * 128;

        #pragma unroll
        for (int ks = 0; ks < 4; ++ks) {
            uint32_t af[4][4], bf[4][2];
            #pragma unroll
            for (int mi = 0; mi < 4; mi++) {
                int row = wm * 64 + mi * 16 + (lane & 15);
                int ch  = 2 * ks + (lane >> 4);
                uint32_t a = abase + row * 128 + ((ch ^ (row & 7)) << 4);
                ldsm4(af[mi][0], af[mi][1], af[mi][2], af[mi][3], a);
            }
            #pragma unroll
            for (int p = 0; p < 2; p++) {
                int row = wn * 32 + p * 16 + ((lane >> 4) << 3) + (lane & 7);
                int ch  = 2 * ks + ((lane >> 3) & 1);
                uint32_t a = bbase + row * 128 + ((ch ^ (row & 7)) << 4);
                ldsm4(bf[2 * p][0], bf[2 * p][1], bf[2 * p + 1][0], bf[2 * p + 1][1], a);
            }
            #pragma unroll
            for (int mi = 0; mi < 4; mi++)
                #pragma unroll
                for (int ni = 0; ni < 4; ni++)
                    HMMA16816(acc[mi][ni], af[mi][0], af[mi][1], af[mi][2], af[mi][3],
                              bf[ni][0], bf[ni][1]);
        }
    }

    // epilogue: accumulate 0.5*mask*f*acc into pre-initialized out
    const float dqw = fmaxf(__uint_as_float(g_wmax[1]), EPSF) * (1.f / 127.f);
    #pragma unroll
    for (int mi = 0; mi < 4; mi++) {
        #pragma unroll
        for (int half = 0; half < 2; ++half) {
            int row = bm + wm * 64 + mi * 16 + (lane >> 2) + half * 8;
            float f = fmaxf(__uint_as_float(g_hmax[row]), EPSF) * (1.f / 127.f) * dqw;
            float c = 0.5f * mask[row] * f;
            #pragma unroll
            for (int ni = 0; ni < 4; ni++) {
                #pragma unroll
                for (int j = 0; j < 2; j++) {
                    int col = bn + wn * 32 + ni * 8 + (lane & 3) * 2 + j;
                    atomicAdd(&out[(size_t)row * DIM + col],
                              c * acc[mi][ni][half * 2 + j]);
                }
            }
        }
    }
}

// ======================= elementwise kernels =======================
__global__ void absmax_both_k(const float4* __restrict__ w1,
                              const float4* __restrict__ w2, int n4) {
    const int wi = blockIdx.y;
    const float4* __restrict__ x = wi ? w2 : w1;
    float m = 0.f;
    for (int i = blockIdx.x * blockDim.x + threadIdx.x; i < n4; i += gridDim.x * blockDim.x) {
        float4 v = x[i];
        m = fmaxf(m, fmaxf(fmaxf(fabsf(v.x), fabsf(v.y)), fmaxf(fabsf(v.z), fabsf(v.w))));
    }
    #pragma unroll
    for (int o = 16; o; o >>= 1) m = fmaxf(m, __shfl_xor_sync(0xffffffffu, m, o));
    __shared__ float sh[32];
    if ((threadIdx.x & 31) == 0) sh[threadIdx.x >> 5] = m;
    __syncthreads();
    if (threadIdx.x < 32) {
        m = (threadIdx.x < (blockDim.x >> 5)) ? sh[threadIdx.x] : 0.f;
        #pragma unroll
        for (int o = 16; o; o >>= 1) m = fmaxf(m, __shfl_xor_sync(0xffffffffu, m, o));
        if (threadIdx.x == 0) atomicMax(&g_wmax[wi], __float_as_uint(m));
    }
}

__global__ void quantw_both_k(const float4* __restrict__ w1,
                              const float4* __restrict__ w2, int n4) {
    const int wi = blockIdx.y;
    const float4* __restrict__ w = wi ? w2 : w1;
    int i = blockIdx.x * blockDim.x + threadIdx.x;
    if (i >= n4) return;
    float s = 127.f / fmaxf(__uint_as_float(g_wmax[wi]), EPSF);
    float4 v = w[i];
    __half2 h0 = __floats2half2_rn(rintf(fminf(fmaxf(v.x * s, -127.f), 127.f)),
                                   rintf(fminf(fmaxf(v.y * s, -127.f), 127.f)));
    __half2 h1 = __floats2half2_rn(rintf(fminf(fmaxf(v.z * s, -127.f), 127.f)),
                                   rintf(fminf(fmaxf(v.w * s, -127.f), 127.f)));
    __half2* dst = (__half2*)(wi ? g_w2h : g_w1h);
    dst[2 * i]     = h0;
    dst[2 * i + 1] = h1;
}

// LN + per-token act quant -> fp16 ints; ALSO pre-initializes
// out = x + 0.5*mask*b2 (GEMM2 epilogue atomically adds the matmul part).
__global__ void ln_quant_k(const float4* __restrict__ x,
                           const float4* __restrict__ gamma,
                           const float4* __restrict__ beta,
                           const float4* __restrict__ b2,
                           const float*  __restrict__ mask,
                           float4* __restrict__ out) {
    const int row = blockIdx.x;
    const int t   = threadIdx.x;           // 256 threads, D/4 = 256 float4
    __shared__ float sh[8];

    float4 v = x[(size_t)row * 256 + t];

    // pre-init out = x + 0.5*mask*b2
    {
        float mk = 0.5f * mask[row];
        float4 b = b2[t];
        float4 o;
        o.x = v.x + mk * b.x;
        o.y = v.y + mk * b.y;
        o.z = v.z + mk * b.z;
        o.w = v.w + mk * b.w;
        out[(size_t)row * 256 + t] = o;
    }

    float s = v.x + v.y + v.z + v.w;
    #pragma unroll
    for (int o = 16; o; o >>= 1) s += __shfl_xor_sync(0xffffffffu, s, o);
    if ((t & 31) == 0) sh[t >> 5] = s;
    __syncthreads();
    float mu = sh[0];
    #pragma unroll
    for (int i = 1; i < 8; i++) mu += sh[i];
    mu *= (1.f / 1024.f);
    __syncthreads();

    float d0 = v.x - mu, d1 = v.y - mu, d2 = v.z - mu, d3 = v.w - mu;
    float ss = d0*d0 + d1*d1 + d2*d2 + d3*d3;
    #pragma unroll
    for (int o = 16; o; o >>= 1) ss += __shfl_xor_sync(0xffffffffu, ss, o);
    if ((t & 31) == 0) sh[t >> 5] = ss;
    __syncthreads();
    float var = sh[0];
    #pragma unroll
    for (int i = 1; i < 8; i++) var += sh[i];
    var *= (1.f / 1024.f);
    __syncthreads();

    float rstd = rsqrtf(var + EPSF);
    float4 g = gamma[t], b = beta[t];
    float y0 = d0 * rstd * g.x + b.x;
    float y1 = d1 * rstd * g.y + b.y;
    float y2 = d2 * rstd * g.z + b.z;
    float y3 = d3 * rstd * g.w + b.w;

    float am = fmaxf(fmaxf(fabsf(y0), fabsf(y1)), fmaxf(fabsf(y2), fabsf(y3)));
    #pragma unroll
    for (int o = 16; o; o >>= 1) am = fmaxf(am, __shfl_xor_sync(0xffffffffu, am, o));
    if ((t & 31) == 0) sh[t >> 5] = am;
    __syncthreads();
    float amax = sh[0];
    #pragma unroll
    for (int i = 1; i < 8; i++) amax = fmaxf(amax, sh[i]);

    amax = fmaxf(amax, EPSF);
    float sc = 127.f / amax;
    __half2 h0 = __floats2half2_rn(rintf(fminf(fmaxf(y0 * sc, -127.f), 127.f)),
                                   rintf(fminf(fmaxf(y1 * sc, -127.f), 127.f)));
    __half2 h1 = __floats2half2_rn(rintf(fminf(fmaxf(y2 * sc, -127.f), 127.f)),
                                   rintf(fminf(fmaxf(y3 * sc, -127.f), 127.f)));
    __half2* dst = (__half2*)g_a1h;
    dst[(size_t)row * 512 + 2 * t]     = h0;
    dst[(size_t)row * 512 + 2 * t + 1] = h1;
    if (t == 0) g_dqa1[row] = amax * (1.f / 127.f);
}

__global__ void quant_h_k() {
    size_t gid = (size_t)blockIdx.x * blockDim.x + threadIdx.x;
    size_t i = gid * 2;
    const float4* __restrict__ src = (const float4*)g_h;
    __half2* __restrict__ dst = (__half2*)g_a2h;
    #pragma unroll
    for (int u = 0; u < 2; u++) {
        size_t idx = i + u;
        int row = (int)(idx >> 10);
        float s = 127.f / fmaxf(__uint_as_float(g_hmax[row]), EPSF);
        float4 v = src[idx];
        __half2 h0 = __floats2half2_rn(rintf(fminf(fmaxf(v.x * s, -127.f), 127.f)),
                                       rintf(fminf(fmaxf(v.y * s, -127.f), 127.f)));
        __half2 h1 = __floats2half2_rn(rintf(fminf(fmaxf(v.z * s, -127.f), 127.f)),
                                       rintf(fminf(fmaxf(v.w * s, -127.f), 127.f)));
        dst[2 * idx]     = h0;
        dst[2 * idx + 1] = h1;
    }
}

// ======================= launcher =======================
extern "C" void kernel_launch(void* const* d_in, const int* in_sizes, int n_in,
                              void* d_out, int out_size) {
    const float* x     = (const float*)d_in[0];
    const float* mask  = (const float*)d_in[1];
    const float* gamma = (const float*)d_in[2];
    const float* beta  = (const float*)d_in[3];
    const float* w1    = (const float*)d_in[4];
    const float* b1    = (const float*)d_in[5];
    const float* w2    = (const float*)d_in[6];
    const float* b2    = (const float*)d_in[7];
    float* out = (float*)d_out;

    const int wn4 = (FF * DIM) / 4;
    const int GEMM_SMEM = 3 * 128 * 128 * 2;       // 96KB
    cudaFuncSetAttribute(gemm1_f16_k, cudaFuncAttributeMaxDynamicSharedMemorySize, GEMM_SMEM);
    cudaFuncSetAttribute(gemm2_f16_k, cudaFuncAttributeMaxDynamicSharedMemorySize, GEMM_SMEM);

    // weights: absmax -> quantize to fp16 ints (idempotent across graph replays)
    absmax_both_k<<<dim3(1024, 2), 256>>>((const float4*)w1, (const float4*)w2, wn4);
    quantw_both_k<<<dim3(wn4 / 256, 2), 256>>>((const float4*)w1, (const float4*)w2, wn4);

    // LN + per-token act quant -> fp16 ints; also out = x + 0.5*mask*b2
    ln_quant_k<<<N_TOK, 256>>>((const float4*)x, (const float4*)gamma, (const float4*)beta,
                               (const float4*)b2, mask, (float4*)out);

    // GEMM1 + swish + row absmax
    gemm1_f16_k<<<dim3(FF / 128, N_TOK / 128), 256, GEMM_SMEM>>>(b1);

    // quantize h -> fp16 ints
    quant_h_k<<<(N_TOK * (FF / 4)) / 512, 256>>>();

    // GEMM2 split-K=2, atomic accumulation into pre-initialized out
    gemm2_f16_k<<<dim3(DIM / 128, N_TOK / 128, 2), 256, GEMM_SMEM>>>(mask, out);
}

// round 13
// speedup vs baseline: 1.2053x; 1.0625x over previous
#include <cuda_runtime.h>
#include <cuda_fp16.h>
#include <cstdint>
#include <math.h>

#define EPSF 1e-5f

static const int N_TOK = 16384;   // B*T = 8*2048
static const int DIM   = 1024;
static const int FF    = 4096;

// ---------------- scratch (device globals; allocation-free) ----------------
__device__ __half   g_w1h[(size_t)FF * DIM];      // 8 MB  (quantized ints as half)
__device__ __half   g_w2h[(size_t)DIM * FF];      // 8 MB
__device__ __half   g_a1h[(size_t)N_TOK * DIM];   // 32 MB
__device__ __half   g_a2h[(size_t)N_TOK * FF];    // 128 MB
__device__ float    g_h  [(size_t)N_TOK * FF];    // 256 MB
__device__ float    g_dqa1[N_TOK];
__device__ unsigned g_hmax[N_TOK];                // float bits, idempotent max
__device__ unsigned g_wmax[2];                    // float bits

// ---------------- small PTX helpers ----------------
__device__ __forceinline__ void cp16(uint32_t dst, const void* src) {
    asm volatile("cp.async.cg.shared.global [%0], [%1], 16;\n" :: "r"(dst), "l"(src));
}
__device__ __forceinline__ void cp_commit() { asm volatile("cp.async.commit_group;\n"); }
template<int N> __device__ __forceinline__ void cp_wait() {
    asm volatile("cp.async.wait_group %0;\n" :: "n"(N));
}
__device__ __forceinline__ void ldsm4(uint32_t& r0, uint32_t& r1, uint32_t& r2, uint32_t& r3,
                                      uint32_t addr) {
    asm volatile("ldmatrix.sync.aligned.m8n8.x4.shared.b16 {%0,%1,%2,%3}, [%4];"
                 : "=r"(r0), "=r"(r1), "=r"(r2), "=r"(r3) : "r"(addr));
}
__device__ __forceinline__ void st_cs_f2(float* p, float a, float b) {
    asm volatile("st.global.cs.v2.f32 [%0], {%1, %2};" :: "l"(p), "f"(a), "f"(b) : "memory");
}
__device__ __forceinline__ float4 ld_cs_f4(const float4* p) {
    float4 v;
    asm volatile("ld.global.cs.v4.f32 {%0,%1,%2,%3}, [%4];"
                 : "=f"(v.x), "=f"(v.y), "=f"(v.z), "=f"(v.w) : "l"(p));
    return v;
}
__device__ __forceinline__ void st_cs_u2(void* p, uint32_t a, uint32_t b) {
    asm volatile("st.global.cs.v2.u32 [%0], {%1, %2};" :: "l"(p), "r"(a), "r"(b) : "memory");
}
#define HMMA16816(acc, a0, a1, a2, a3, b0, b1) \
    asm volatile("mma.sync.aligned.m16n8k16.row.col.f32.f16.f16.f32 " \
                 "{%0,%1,%2,%3}, {%4,%5,%6,%7}, {%8,%9}, {%0,%1,%2,%3};\n" \
                 : "+f"((acc)[0]), "+f"((acc)[1]), "+f"((acc)[2]), "+f"((acc)[3]) \
                 : "r"(a0), "r"(a1), "r"(a2), "r"(a3), "r"(b0), "r"(b1))

// ======================= fp16 GEMM via mma.sync m16n8k16 (R8 config) ===========
// BM=128, BN=128, BK=64 (128B rows). 256 threads = 8 warps as 2(m) x 4(n),
// warp tile 64x32. 3-stage cp.async pipeline, 96KB smem/CTA, 2 CTAs/SM.
// Smem swizzle: 16B chunk' = chunk ^ (row & 7).
//
// EPI==1: g_h = swish(dq(a1 @ w1^T) + b1) [streaming .cs stores], rowmax->g_hmax
// EPI==2: out = x + 0.5*mask*(dq(a2 @ w2^T) + b2)
template<int EPI>
__launch_bounds__(256, 2)
__global__ void gemm_f16_k(const float* __restrict__ bias,
                           const float* __restrict__ xres,
                           const float* __restrict__ mask,
                           float* __restrict__ out) {
    constexpr int K  = (EPI == 1) ? DIM : FF;        // elements (halves)
    constexpr int KT = K / 64;                       // BK=64 slabs
    constexpr int STAGE = 128 * 128 * 2;             // A 16KB + B 16KB = 32KB

    const __half* __restrict__ A  = (EPI == 1) ? g_a1h : g_a2h;
    const __half* __restrict__ Bw = (EPI == 1) ? g_w1h : g_w2h;

    extern __shared__ int8_t sm[];                   // 3 * 32KB

    const int tid  = threadIdx.x;
    const int lane = tid & 31;
    const int warp = tid >> 5;
    const int wm   = warp >> 2;                      // 0..1
    const int wn   = warp & 3;                       // 0..3
    const int bm   = blockIdx.y * 128;
    const int bn   = blockIdx.x * 128;

    float acc[4][4][4];
    #pragma unroll
    for (int mi = 0; mi < 4; mi++)
        #pragma unroll
        for (int ni = 0; ni < 4; ni++)
            #pragma unroll
            for (int j = 0; j < 4; j++) acc[mi][ni][j] = 0.f;

    auto ld_stage = [&](int stg, int kt) {
        uint32_t ab = (uint32_t)__cvta_generic_to_shared(sm + stg * STAGE);
        uint32_t bb = ab + 128 * 128;
        #pragma unroll
        for (int i = 0; i < 4; i++) {                // A: 1024 chunks of 16B
            int c = tid + i * 256;
            int row = c >> 3, ch = c & 7;
            uint32_t dst = ab + row * 128 + ((ch ^ (row & 7)) << 4);
            cp16(dst, (const int8_t*)A + (size_t)(bm + row) * (K * 2) + kt * 128 + ch * 16);
        }
        #pragma unroll
        for (int i = 0; i < 4; i++) {                // B: 1024 chunks of 16B
            int c = tid + i * 256;
            int row = c >> 3, ch = c & 7;
            uint32_t dst = bb + row * 128 + ((ch ^ (row & 7)) << 4);
            cp16(dst, (const int8_t*)Bw + (size_t)(bn + row) * (K * 2) + kt * 128 + ch * 16);
        }
        cp_commit();
    };

    ld_stage(0, 0);
    ld_stage(1, 1);

    for (int kt = 0; kt < KT; ++kt) {
        if (kt + 2 < KT) { cp_wait<1>(); } else { cp_wait<0>(); }
        __syncthreads();
        if (kt + 2 < KT) ld_stage((kt + 2) % 3, kt + 2);

        uint32_t abase = (uint32_t)__cvta_generic_to_shared(sm + (kt % 3) * STAGE);
        uint32_t bbase = abase + 128 * 128;

        #pragma unroll
        for (int ks = 0; ks < 4; ++ks) {             // four k16 steps per slab
            uint32_t af[4][4], bf[4][2];
            #pragma unroll
            for (int mi = 0; mi < 4; mi++) {
                int row = wm * 64 + mi * 16 + (lane & 15);
                int ch  = 2 * ks + (lane >> 4);
                uint32_t a = abase + row * 128 + ((ch ^ (row & 7)) << 4);
                ldsm4(af[mi][0], af[mi][1], af[mi][2], af[mi][3], a);
            }
            #pragma unroll
            for (int p = 0; p < 2; p++) {
                int row = wn * 32 + p * 16 + ((lane >> 4) << 3) + (lane & 7);
                int ch  = 2 * ks + ((lane >> 3) & 1);
                uint32_t a = bbase + row * 128 + ((ch ^ (row & 7)) << 4);
                ldsm4(bf[2 * p][0], bf[2 * p][1], bf[2 * p + 1][0], bf[2 * p + 1][1], a);
            }
            #pragma unroll
            for (int mi = 0; mi < 4; mi++)
                #pragma unroll
                for (int ni = 0; ni < 4; ni++)
                    HMMA16816(acc[mi][ni], af[mi][0], af[mi][1], af[mi][2], af[mi][3],
                              bf[ni][0], bf[ni][1]);
        }
    }

    // ---------------- epilogue ----------------
    const float dqw = fmaxf(__uint_as_float(g_wmax[EPI - 1]), EPSF) * (1.f / 127.f);

    if (EPI == 1) {
        #pragma unroll
        for (int mi = 0; mi < 4; mi++) {
            #pragma unroll
            for (int half = 0; half < 2; ++half) {
                int row = bm + wm * 64 + mi * 16 + (lane >> 2) + half * 8;
                float f = g_dqa1[row] * dqw;
                float rmax = 0.f;
                #pragma unroll
                for (int ni = 0; ni < 4; ni++) {
                    int col = bn + wn * 32 + ni * 8 + (lane & 3) * 2;
                    float v0 = acc[mi][ni][half * 2 + 0] * f + __ldg(&bias[col]);
                    float v1 = acc[mi][ni][half * 2 + 1] * f + __ldg(&bias[col + 1]);
                    float h0 = v0 / (1.f + __expf(-v0));       // v * sigmoid(v)
                    float h1 = v1 / (1.f + __expf(-v1));
                    st_cs_f2(&g_h[(size_t)row * FF + col], h0, h1);  // streaming store
                    rmax = fmaxf(rmax, fmaxf(fabsf(h0), fabsf(h1)));
                }
                rmax = fmaxf(rmax, __shfl_xor_sync(0xffffffffu, rmax, 1));
                rmax = fmaxf(rmax, __shfl_xor_sync(0xffffffffu, rmax, 2));
                if ((lane & 3) == 0) atomicMax(&g_hmax[row], __float_as_uint(rmax));
            }
        }
    } else {
        #pragma unroll
        for (int mi = 0; mi < 4; mi++) {
            #pragma unroll
            for (int half = 0; half < 2; ++half) {
                int row = bm + wm * 64 + mi * 16 + (lane >> 2) + half * 8;
                float f  = fmaxf(__uint_as_float(g_hmax[row]), EPSF) * (1.f / 127.f) * dqw;
                float mk = mask[row];
                #pragma unroll
                for (int ni = 0; ni < 4; ni++) {
                    int col = bn + wn * 32 + ni * 8 + (lane & 3) * 2;
                    float v0 = acc[mi][ni][half * 2 + 0] * f + __ldg(&bias[col]);
                    float v1 = acc[mi][ni][half * 2 + 1] * f + __ldg(&bias[col + 1]);
                    const float2 xv = *(const float2*)&xres[(size_t)row * DIM + col];
                    st_cs_f2(&out[(size_t)row * DIM + col],
                             xv.x + 0.5f * v0 * mk, xv.y + 0.5f * v1 * mk);
                }
            }
        }
    }
}

// ======================= elementwise kernels =======================
__global__ void absmax_both_k(const float4* __restrict__ w1,
                              const float4* __restrict__ w2, int n4) {
    const int wi = blockIdx.y;
    const float4* __restrict__ x = wi ? w2 : w1;
    float m = 0.f;
    for (int i = blockIdx.x * blockDim.x + threadIdx.x; i < n4; i += gridDim.x * blockDim.x) {
        float4 v = x[i];
        m = fmaxf(m, fmaxf(fmaxf(fabsf(v.x), fabsf(v.y)), fmaxf(fabsf(v.z), fabsf(v.w))));
    }
    #pragma unroll
    for (int o = 16; o; o >>= 1) m = fmaxf(m, __shfl_xor_sync(0xffffffffu, m, o));
    __shared__ float sh[32];
    if ((threadIdx.x & 31) == 0) sh[threadIdx.x >> 5] = m;
    __syncthreads();
    if (threadIdx.x < 32) {
        m = (threadIdx.x < (blockDim.x >> 5)) ? sh[threadIdx.x] : 0.f;
        #pragma unroll
        for (int o = 16; o; o >>= 1) m = fmaxf(m, __shfl_xor_sync(0xffffffffu, m, o));
        if (threadIdx.x == 0) atomicMax(&g_wmax[wi], __float_as_uint(m));
    }
}

__global__ void quantw_both_k(const float4* __restrict__ w1,
                              const float4* __restrict__ w2, int n4) {
    const int wi = blockIdx.y;
    const float4* __restrict__ w = wi ? w2 : w1;
    int i = blockIdx.x * blockDim.x + threadIdx.x;
    if (i >= n4) return;
    float s = 127.f / fmaxf(__uint_as_float(g_wmax[wi]), EPSF);
    float4 v = w[i];
    __half2 h0 = __floats2half2_rn(rintf(fminf(fmaxf(v.x * s, -127.f), 127.f)),
                                   rintf(fminf(fmaxf(v.y * s, -127.f), 127.f)));
    __half2 h1 = __floats2half2_rn(rintf(fminf(fmaxf(v.z * s, -127.f), 127.f)),
                                   rintf(fminf(fmaxf(v.w * s, -127.f), 127.f)));
    __half2* dst = (__half2*)(wi ? g_w2h : g_w1h);
    dst[2 * i]     = h0;
    dst[2 * i + 1] = h1;
}

__global__ void ln_quant_k(const float4* __restrict__ x,
                           const float4* __restrict__ gamma,
                           const float4* __restrict__ beta) {
    const int row = blockIdx.x;
    const int t   = threadIdx.x;           // 256 threads, D/4 = 256 float4
    __shared__ float sh[8];

    float4 v = x[(size_t)row * 256 + t];
    float s = v.x + v.y + v.z + v.w;
    #pragma unroll
    for (int o = 16; o; o >>= 1) s += __shfl_xor_sync(0xffffffffu, s, o);
    if ((t & 31) == 0) sh[t >> 5] = s;
    __syncthreads();
    float mu = sh[0];
    #pragma unroll
    for (int i = 1; i < 8; i++) mu += sh[i];
    mu *= (1.f / 1024.f);
    __syncthreads();

    float d0 = v.x - mu, d1 = v.y - mu, d2 = v.z - mu, d3 = v.w - mu;
    float ss = d0*d0 + d1*d1 + d2*d2 + d3*d3;
    #pragma unroll
    for (int o = 16; o; o >>= 1) ss += __shfl_xor_sync(0xffffffffu, ss, o);
    if ((t & 31) == 0) sh[t >> 5] = ss;
    __syncthreads();
    float var = sh[0];
    #pragma unroll
    for (int i = 1; i < 8; i++) var += sh[i];
    var *= (1.f / 1024.f);
    __syncthreads();

    float rstd = rsqrtf(var + EPSF);
    float4 g = gamma[t], b = beta[t];
    float y0 = d0 * rstd * g.x + b.x;
    float y1 = d1 * rstd * g.y + b.y;
    float y2 = d2 * rstd * g.z + b.z;
    float y3 = d3 * rstd * g.w + b.w;

    float am = fmaxf(fmaxf(fabsf(y0), fabsf(y1)), fmaxf(fabsf(y2), fabsf(y3)));
    #pragma unroll
    for (int o = 16; o; o >>= 1) am = fmaxf(am, __shfl_xor_sync(0xffffffffu, am, o));
    if ((t & 31) == 0) sh[t >> 5] = am;
    __syncthreads();
    float amax = sh[0];
    #pragma unroll
    for (int i = 1; i < 8; i++) amax = fmaxf(amax, sh[i]);

    amax = fmaxf(amax, EPSF);
    float sc = 127.f / amax;
    __half2 h0 = __floats2half2_rn(rintf(fminf(fmaxf(y0 * sc, -127.f), 127.f)),
                                   rintf(fminf(fmaxf(y1 * sc, -127.f), 127.f)));
    __half2 h1 = __floats2half2_rn(rintf(fminf(fmaxf(y2 * sc, -127.f), 127.f)),
                                   rintf(fminf(fmaxf(y3 * sc, -127.f), 127.f)));
    __half2* dst = (__half2*)g_a1h;
    dst[(size_t)row * 512 + 2 * t]     = h0;
    dst[(size_t)row * 512 + 2 * t + 1] = h1;
    if (t == 0) g_dqa1[row] = amax * (1.f / 127.f);
}

// Pure 384MB stream: .cs loads + .cs stores keep it out of L2.
__global__ void quant_h_k() {
    size_t gid = (size_t)blockIdx.x * blockDim.x + threadIdx.x;
    size_t i = gid * 2;
    const float4* __restrict__ src = (const float4*)g_h;
    #pragma unroll
    for (int u = 0; u < 2; u++) {
        size_t idx = i + u;
        int row = (int)(idx >> 10);                  // FF/4 = 1024 float4 per row
        float s = 127.f / fmaxf(__uint_as_float(g_hmax[row]), EPSF);
        float4 v = ld_cs_f4(src + idx);
        __half2 h0 = __floats2half2_rn(rintf(fminf(fmaxf(v.x * s, -127.f), 127.f)),
                                       rintf(fminf(fmaxf(v.y * s, -127.f), 127.f)));
        __half2 h1 = __floats2half2_rn(rintf(fminf(fmaxf(v.z * s, -127.f), 127.f)),
                                       rintf(fminf(fmaxf(v.w * s, -127.f), 127.f)));
        st_cs_u2((uint32_t*)g_a2h + 2 * idx,
                 *(uint32_t*)&h0, *(uint32_t*)&h1);
    }
}

// ======================= launcher =======================
extern "C" void kernel_launch(void* const* d_in, const int* in_sizes, int n_in,
                              void* d_out, int out_size) {
    const float* x     = (const float*)d_in[0];
    const float* mask  = (const float*)d_in[1];
    const float* gamma = (const float*)d_in[2];
    const float* beta  = (const float*)d_in[3];
    const float* w1    = (const float*)d_in[4];
    const float* b1    = (const float*)d_in[5];
    const float* w2    = (const float*)d_in[6];
    const float* b2    = (const float*)d_in[7];
    float* out = (float*)d_out;

    const int wn4 = (FF * DIM) / 4;
    const int GEMM_SMEM = 3 * 128 * 128 * 2;       // 96KB
    cudaFuncSetAttribute(gemm_f16_k<1>, cudaFuncAttributeMaxDynamicSharedMemorySize, GEMM_SMEM);
    cudaFuncSetAttribute(gemm_f16_k<2>, cudaFuncAttributeMaxDynamicSharedMemorySize, GEMM_SMEM);

    // weights: absmax -> quantize to fp16 ints (idempotent across graph replays)
    absmax_both_k<<<dim3(1024, 2), 256>>>((const float4*)w1, (const float4*)w2, wn4);
    quantw_both_k<<<dim3(wn4 / 256, 2), 256>>>((const float4*)w1, (const float4*)w2, wn4);

    // LN + per-token act quant -> fp16 ints
    ln_quant_k<<<N_TOK, 256>>>((const float4*)x, (const float4*)gamma, (const float4*)beta);

    // GEMM1 + swish + row absmax (streaming h stores protect L2-resident panels)
    gemm_f16_k<1><<<dim3(FF / 128, N_TOK / 128), 256, GEMM_SMEM>>>(b1, nullptr, nullptr, nullptr);

    // quantize h -> fp16 ints
    quant_h_k<<<(N_TOK * (FF / 4)) / 512, 256>>>();

    // GEMM2 + residual
    gemm_f16_k<2><<<dim3(DIM / 128, N_TOK / 128), 256, GEMM_SMEM>>>(b2, x, mask, out);
}